// round 6
// baseline (speedup 1.0000x reference)
#include <cuda_runtime.h>

#define BB 4096
#define TT 2048
#define II 4
#define HH 3

typedef unsigned long long u64;

__device__ __forceinline__ float tanh_ap(float x) {
    float y; asm("tanh.approx.f32 %0, %1;" : "=f"(y) : "f"(x)); return y;
}
__device__ __forceinline__ u64 fma2(u64 a, u64 b, u64 c) {
    u64 d; asm("fma.rn.f32x2 %0, %1, %2, %3;" : "=l"(d) : "l"(a), "l"(b), "l"(c)); return d;
}
__device__ __forceinline__ u64 mul2(u64 a, u64 b) {
    u64 d; asm("mul.rn.f32x2 %0, %1, %2;" : "=l"(d) : "l"(a), "l"(b)); return d;
}
__device__ __forceinline__ u64 pk2(float lo, float hi) {
    u64 d; asm("mov.b64 %0, {%1, %2};" : "=l"(d) : "f"(lo), "f"(hi)); return d;
}
__device__ __forceinline__ void up2(u64 v, float& lo, float& hi) {
    asm("mov.b64 {%0, %1}, %2;" : "=f"(lo), "=f"(hi) : "l"(v));
}

// Topology: 4 lanes per GROUP; lane sub=0,1,2 owns hidden unit sub (lane 3
// duplicates unit 2 for convergence). Each group carries a PAIR of sequences
// (2g, 2g+1) packed into the lo/hi halves of f32x2 registers — the pair
// shares every instruction, so one ~60-instr walk advances 2 sequences.
// Warp = 8 groups = 16 sequences (adjacent sorted lengths -> balanced).
// Per-warp-step cost: ~60 issue, 10 MUFU (rt-floor 80), chain ~100 cyc.
// Wall = longest warp's walk: 2048 * walk.
// sigmoid(z) = 0.5*tanh(0.5 z)+0.5 with sigmoid rows pre-scaled by 0.5.
// 64 blocks x 128 threads: 4 warps/block, one per SMSP; the longest block
// gets its own SM so critical warps run solo (full MUFU rate).
__global__ void __launch_bounds__(128)
lstm_main(const float* __restrict__ x,
          const float* __restrict__ Wih,
          const float* __restrict__ Whh,
          const float* __restrict__ bih,
          const float* __restrict__ bhh,
          const int*   __restrict__ lenw,
          float* __restrict__ out)
{
    const int tid  = threadIdx.x;
    const int lane = tid & 31;
    const int sub  = lane & 3;
    const int base = lane & ~3;
    const int g    = blockIdx.x * 32 + (tid >> 2);   // 0..2047
    const int bA   = 2 * g;
    const int bB   = 2 * g + 1;
    const int unit = (sub < 3) ? sub : 2;

    // length dtype sniff (lengths >= 1, so int32 elem 1 == 0 => int64 words)
    const bool is64 = (lenw[1] == 0);
    int lenA = is64 ? lenw[2 * bA] : lenw[bA];
    int lenB = is64 ? lenw[2 * bB] : lenw[bB];
    lenA = min(max(lenA, 1), TT);
    lenB = min(max(lenB, 1), TT);   // sorted desc: lenB <= lenA

    // warp trip = longest seq among the warp's 16, rounded up to chunk of 4
    const int trip = (__reduce_max_sync(0xffffffffu, lenA) + 3) & ~3;

    // per-unit gate rows: i=unit, f=3+unit, g=6+unit, o=9+unit
    const int ri = unit, rf = 3 + unit, rg = 6 + unit, ro = 9 + unit;
    const float SI = 0.5f, SG = 1.0f;

    // input weights, splat into both f32x2 halves (pair shares weights)
    u64 wxi[II], wxf[II], wxg[II], wxo[II];
    #pragma unroll
    for (int k = 0; k < II; k++) {
        const float a = SI * Wih[ri * II + k]; wxi[k] = pk2(a, a);
        const float f = SI * Wih[rf * II + k]; wxf[k] = pk2(f, f);
        const float gg = SG * Wih[rg * II + k]; wxg[k] = pk2(gg, gg);
        const float o = SI * Wih[ro * II + k]; wxo[k] = pk2(o, o);
    }
    u64 whi[HH], whf[HH], whg[HH], who[HH];
    #pragma unroll
    for (int k = 0; k < HH; k++) {
        const float a = SI * Whh[ri * HH + k]; whi[k] = pk2(a, a);
        const float f = SI * Whh[rf * HH + k]; whf[k] = pk2(f, f);
        const float gg = SG * Whh[rg * HH + k]; whg[k] = pk2(gg, gg);
        const float o = SI * Whh[ro * HH + k]; who[k] = pk2(o, o);
    }
    const float biS = SI * (bih[ri] + bhh[ri]);
    const float bfS = SI * (bih[rf] + bhh[rf]);
    const float bgS = SG * (bih[rg] + bhh[rg]);
    const float boS = SI * (bih[ro] + bhh[ro]);
    const u64 bi2 = pk2(biS, biS), bf2 = pk2(bfS, bfS);
    const u64 bg2 = pk2(bgS, bgS), bo2 = pk2(boS, boS);
    const u64 HALF2 = pk2(0.5f, 0.5f);

    // state: h pairs (unit0,1,2) and c pair
    u64 hh0 = 0, hh1 = 0, hh2 = 0, c2 = 0;

    const float4* __restrict__ xrA = (const float4*)(x + (size_t)bA * TT * II);
    const float4* __restrict__ xrB = (const float4*)(x + (size_t)bB * TT * II);
    float* __restrict__ orowA = out + (size_t)bA * TT * HH;
    float* __restrict__ orowB = out + (size_t)bB * TT * HH;

    // one-chunk-ahead prefetch (4 steps * ~150cyc ~= 600 > DRAM 577)
    float4 bufA[4], bufB[4];
    #pragma unroll
    for (int p = 0; p < 4; p++) { bufA[p] = __ldg(&xrA[p]); bufB[p] = __ldg(&xrB[p]); }

    const int nch = trip >> 2;
    for (int tc = 0; tc < nch; tc++) {
        #pragma unroll
        for (int u = 0; u < 4; u++) {
            const int t = 4 * tc + u;
            const float4 xa = bufA[u];
            const float4 xb = bufB[u];
            const int nt = t + 4;
            bufA[u] = __ldg(&xrA[min(nt, TT - 1)]);
            bufB[u] = __ldg(&xrB[min(nt, TT - 1)]);

            // pack (A,B) input pairs
            const u64 xx0 = pk2(xa.x, xb.x), xx1 = pk2(xa.y, xb.y);
            const u64 xx2 = pk2(xa.z, xb.z), xx3 = pk2(xa.w, xb.w);

            // input projection (independent of recurrence)
            u64 zi = fma2(xx0, wxi[0], bi2); zi = fma2(xx1, wxi[1], zi);
            zi = fma2(xx2, wxi[2], zi);      zi = fma2(xx3, wxi[3], zi);
            u64 zf = fma2(xx0, wxf[0], bf2); zf = fma2(xx1, wxf[1], zf);
            zf = fma2(xx2, wxf[2], zf);      zf = fma2(xx3, wxf[3], zf);
            u64 zg = fma2(xx0, wxg[0], bg2); zg = fma2(xx1, wxg[1], zg);
            zg = fma2(xx2, wxg[2], zg);      zg = fma2(xx3, wxg[3], zg);
            u64 zo = fma2(xx0, wxo[0], bo2); zo = fma2(xx1, wxo[1], zo);
            zo = fma2(xx2, wxo[2], zo);      zo = fma2(xx3, wxo[3], zo);

            // recurrent projection (critical path)
            zi = fma2(hh0, whi[0], zi); zi = fma2(hh1, whi[1], zi); zi = fma2(hh2, whi[2], zi);
            zf = fma2(hh0, whf[0], zf); zf = fma2(hh1, whf[1], zf); zf = fma2(hh2, whf[2], zf);
            zg = fma2(hh0, whg[0], zg); zg = fma2(hh1, whg[1], zg); zg = fma2(hh2, whg[2], zg);
            zo = fma2(hh0, who[0], zo); zo = fma2(hh1, who[1], zo); zo = fma2(hh2, who[2], zo);

            float ziA, ziB, zfA, zfB, zgA, zgB, zoA, zoB;
            up2(zi, ziA, ziB); up2(zf, zfA, zfB);
            up2(zg, zgA, zgB); up2(zo, zoA, zoB);

            const u64 ti2 = pk2(tanh_ap(ziA), tanh_ap(ziB));
            const u64 tf2 = pk2(tanh_ap(zfA), tanh_ap(zfB));
            const u64 tg2 = pk2(tanh_ap(zgA), tanh_ap(zgB));
            const u64 to2 = pk2(tanh_ap(zoA), tanh_ap(zoB));

            const u64 si2 = fma2(ti2, HALF2, HALF2);
            const u64 sf2 = fma2(tf2, HALF2, HALF2);
            const u64 so2 = fma2(to2, HALF2, HALF2);

            c2 = fma2(sf2, c2, mul2(si2, tg2));

            float cA, cB; up2(c2, cA, cB);
            const u64 tc2 = pk2(tanh_ap(cA), tanh_ap(cB));
            const u64 h2  = mul2(so2, tc2);

            float hA, hB; up2(h2, hA, hB);

            // broadcast the 3 unit h-pairs within the group (warp-uniform flow)
            const float l0 = __shfl_sync(0xffffffffu, hA, base + 0);
            const float h0h = __shfl_sync(0xffffffffu, hB, base + 0);
            const float l1 = __shfl_sync(0xffffffffu, hA, base + 1);
            const float h1h = __shfl_sync(0xffffffffu, hB, base + 1);
            const float l2 = __shfl_sync(0xffffffffu, hA, base + 2);
            const float h2h = __shfl_sync(0xffffffffu, hB, base + 2);
            hh0 = pk2(l0, h0h);
            hh1 = pk2(l1, h1h);
            hh2 = pk2(l2, h2h);

            // predicated stores (only valid timesteps; lane 3 is a duplicate)
            if (sub < 3 && t < lenA) orowA[t * HH + unit] = hA;
            if (sub < 3 && t < lenB) orowB[t * HH + unit] = hB;
        }
    }

    // cooperative tail-zero of the warp's 16 sequences: floats [len*3, 6144).
    // Disjoint from the loop's predicated stores -> no ordering hazard.
    const int gw0 = blockIdx.x * 32 + ((tid >> 5) << 3);  // warp's first group
    #pragma unroll
    for (int j = 0; j < 8; j++) {
        const int lA = __shfl_sync(0xffffffffu, lenA, (tid & ~31 & 31) + 0 + j * 4) ;
        const int lB = __shfl_sync(0xffffffffu, lenB, j * 4);
        (void)lA;
        // (shfl src is lane index within warp: group j base lane = 4*j)
        const int LA = __shfl_sync(0xffffffffu, lenA, j * 4);
        const int seqA = 2 * (gw0 + j);
        const int seqB = seqA + 1;
        // seq A
        {
            float* row = out + (size_t)seqA * TT * HH;
            const int startf = LA * HH;
            const int v4 = (startf + 3) >> 2;
            const int head = v4 * 4 - startf;           // 0..3 scalar elems
            if (lane < head && startf + lane < TT * HH) row[startf + lane] = 0.0f;
            float4* r4 = (float4*)row;
            for (int i = v4 + lane; i < (TT * HH) / 4; i += 32)
                r4[i] = make_float4(0.f, 0.f, 0.f, 0.f);
        }
        // seq B
        {
            float* row = out + (size_t)seqB * TT * HH;
            const int startf = lB * HH;
            const int v4 = (startf + 3) >> 2;
            const int head = v4 * 4 - startf;
            if (lane < head && startf + lane < TT * HH) row[startf + lane] = 0.0f;
            float4* r4 = (float4*)row;
            for (int i = v4 + lane; i < (TT * HH) / 4; i += 32)
                r4[i] = make_float4(0.f, 0.f, 0.f, 0.f);
        }
    }
}

extern "C" void kernel_launch(void* const* d_in, const int* in_sizes, int n_in,
                              void* d_out, int out_size)
{
    const float* x   = (const float*)d_in[0];
    const float* Wih = (const float*)d_in[1];
    const float* Whh = (const float*)d_in[2];
    const float* bih = (const float*)d_in[3];
    const float* bhh = (const float*)d_in[4];
    const int*   len = (const int*)  d_in[5];
    float* out = (float*)d_out;
    (void)in_sizes; (void)n_in; (void)out_size;

    // 2048 groups * 4 lanes = 8192 threads = 64 blocks x 128 (4 warps/block)
    lstm_main<<<64, 128>>>(x, Wih, Whh, bih, bhh, len, out);
}

// round 7
// speedup vs baseline: 1.1699x; 1.1699x over previous
#include <cuda_runtime.h>

#define BB 4096
#define TT 2048
#define II 4
#define HH 3

__device__ __forceinline__ float tanh_ap(float x) {
    float y; asm("tanh.approx.f32 %0, %1;" : "=f"(y) : "f"(x)); return y;
}

// R1 topology (best measured: 322 cyc/step) + tanh activations + 2 warps/SMSP.
// 4 lanes per sequence; lane sub=0,1,2 owns hidden unit sub (lane 3 duplicates
// unit 2 so the quad stays converged). Scalar math only — no f32x2, no
// pack/unpack on the chain (R6 showed those cost ~70 cyc/step).
// sigmoid(z) = 0.5*tanh(0.5z)+0.5 with sigmoid rows pre-scaled by 0.5.
// Per warp-step: ~40 instrs, 5 MUFU (floor 40), chain ~90 cyc.
// 64 blocks x 256 threads: 8 warps/block, 1 block/SM -> 2 warps per SMSP,
// so co-resident warps hide each other's chain latency without saturating
// MUFU (2x5x8 = 80 cyc per 2-warp window).
__global__ void __launch_bounds__(256)
lstm_main(const float* __restrict__ x,
          const float* __restrict__ Wih,
          const float* __restrict__ Whh,
          const float* __restrict__ bih,
          const float* __restrict__ bhh,
          const int*   __restrict__ lenw,
          float* __restrict__ out)
{
    const int tid  = threadIdx.x;
    const int lane = tid & 31;
    const int sub  = lane & 3;
    const int base = lane & ~3;
    const int b    = blockIdx.x * 64 + (tid >> 2);   // 64 blocks * 64 seqs
    const int unit = (sub < 3) ? sub : 2;

    // length dtype sniff (lengths >= 1, so int32 elem 1 == 0 => int64 words)
    const bool is64 = (lenw[1] == 0);
    int len = is64 ? lenw[2 * b] : lenw[b];
    len = min(max(len, 1), TT);

    // warp-uniform trip count (max over the warp's 8 seqs), chunk of 4
    const int trip = (__reduce_max_sync(0xffffffffu, len) + 3) & ~3;

    const int ri = unit, rf = 3 + unit, rg = 6 + unit, ro = 9 + unit;
    const float SI = 0.5f, SG = 1.0f;

    float wxi[II], wxf[II], wxg[II], wxo[II];
    #pragma unroll
    for (int k = 0; k < II; k++) {
        wxi[k] = SI * Wih[ri * II + k];
        wxf[k] = SI * Wih[rf * II + k];
        wxg[k] = SG * Wih[rg * II + k];
        wxo[k] = SI * Wih[ro * II + k];
    }
    float whi[HH], whf[HH], whg[HH], who[HH];
    #pragma unroll
    for (int k = 0; k < HH; k++) {
        whi[k] = SI * Whh[ri * HH + k];
        whf[k] = SI * Whh[rf * HH + k];
        whg[k] = SG * Whh[rg * HH + k];
        who[k] = SI * Whh[ro * HH + k];
    }
    const float bi = SI * (bih[ri] + bhh[ri]);
    const float bf = SI * (bih[rf] + bhh[rf]);
    const float bg = SG * (bih[rg] + bhh[rg]);
    const float bo = SI * (bih[ro] + bhh[ro]);

    float h0 = 0.f, h1 = 0.f, h2 = 0.f, c = 0.f;

    const float4* __restrict__ xr = (const float4*)(x + (size_t)b * TT * II);
    float* __restrict__ orow = out + (size_t)b * TT * HH;

    // one-chunk-ahead prefetch ring (4 steps * ~120cyc ~= 500; L1/L2 resident
    // after first touch since all 4 lanes of the quad read the same row)
    float4 buf[4];
    #pragma unroll
    for (int p = 0; p < 4; p++) buf[p] = __ldg(&xr[p]);

    const int nch = trip >> 2;
    for (int tc = 0; tc < nch; tc++) {
        #pragma unroll
        for (int u = 0; u < 4; u++) {
            const int t = 4 * tc + u;
            const float4 xv = buf[u];
            buf[u] = __ldg(&xr[min(t + 4, TT - 1)]);

            // input projection (independent of recurrence)
            float ai = bi, af = bf, ag = bg, ao = bo;
            ai = fmaf(xv.x, wxi[0], ai); ai = fmaf(xv.y, wxi[1], ai);
            ai = fmaf(xv.z, wxi[2], ai); ai = fmaf(xv.w, wxi[3], ai);
            af = fmaf(xv.x, wxf[0], af); af = fmaf(xv.y, wxf[1], af);
            af = fmaf(xv.z, wxf[2], af); af = fmaf(xv.w, wxf[3], af);
            ag = fmaf(xv.x, wxg[0], ag); ag = fmaf(xv.y, wxg[1], ag);
            ag = fmaf(xv.z, wxg[2], ag); ag = fmaf(xv.w, wxg[3], ag);
            ao = fmaf(xv.x, wxo[0], ao); ao = fmaf(xv.y, wxo[1], ao);
            ao = fmaf(xv.z, wxo[2], ao); ao = fmaf(xv.w, wxo[3], ao);

            // recurrent projection (critical path starts here)
            ai = fmaf(h0, whi[0], ai); ai = fmaf(h1, whi[1], ai); ai = fmaf(h2, whi[2], ai);
            af = fmaf(h0, whf[0], af); af = fmaf(h1, whf[1], af); af = fmaf(h2, whf[2], af);
            ag = fmaf(h0, whg[0], ag); ag = fmaf(h1, whg[1], ag); ag = fmaf(h2, whg[2], ag);
            ao = fmaf(h0, who[0], ao); ao = fmaf(h1, who[1], ao); ao = fmaf(h2, who[2], ao);

            const float ti = tanh_ap(ai);
            const float tf = tanh_ap(af);
            const float tg = tanh_ap(ag);
            const float to_ = tanh_ap(ao);
            const float si = fmaf(ti, 0.5f, 0.5f);
            const float sf = fmaf(tf, 0.5f, 0.5f);
            const float so = fmaf(to_, 0.5f, 0.5f);

            c = fmaf(sf, c, si * tg);
            const float hn = so * tanh_ap(c);

            h0 = __shfl_sync(0xffffffffu, hn, base + 0);
            h1 = __shfl_sync(0xffffffffu, hn, base + 1);
            h2 = __shfl_sync(0xffffffffu, hn, base + 2);

            if (sub < 3 && t < len) orow[t * HH + unit] = hn;
        }
    }

    // warp-cooperative zero of the 8 sequences' poisoned tails [len*3, 6144).
    // Disjoint from the loop's predicated stores -> no ordering hazard.
    const int w   = lane;                         // 0..31
    const int sb0 = blockIdx.x * 64 + ((tid >> 5) << 3);   // warp's first seq
    #pragma unroll
    for (int j = 0; j < 8; j++) {
        const int lj  = __shfl_sync(0xffffffffu, len, 4 * j);  // len of group j
        float* row = out + (size_t)(sb0 + j) * TT * HH;
        const int startf = lj * HH;
        const int v4   = (startf + 3) >> 2;       // first full float4 slot
        const int head = v4 * 4 - startf;         // 0..3 scalar elems
        if (w < head && startf + w < TT * HH) row[startf + w] = 0.0f;
        float4* r4 = (float4*)row;
        for (int i = v4 + w; i < (TT * HH) / 4; i += 32)
            r4[i] = make_float4(0.f, 0.f, 0.f, 0.f);
    }
}

extern "C" void kernel_launch(void* const* d_in, const int* in_sizes, int n_in,
                              void* d_out, int out_size)
{
    const float* x   = (const float*)d_in[0];
    const float* Wih = (const float*)d_in[1];
    const float* Whh = (const float*)d_in[2];
    const float* bih = (const float*)d_in[3];
    const float* bhh = (const float*)d_in[4];
    const int*   len = (const int*)  d_in[5];
    float* out = (float*)d_out;
    (void)in_sizes; (void)n_in; (void)out_size;

    // 4096 seqs * 4 lanes = 16384 threads = 64 blocks x 256
    // (8 warps/block -> 2 warps per SMSP, 1 block/SM)
    lstm_main<<<64, 256>>>(x, Wih, Whh, bih, bhh, len, out);
}